// round 2
// baseline (speedup 1.0000x reference)
#include <cuda_runtime.h>
#include <math.h>

// Shapes (fixed per reference)
// N=8, Cp=2048, H=W=64 (HW=4096), Cq=256, L=128, NH=8, KD=128, VD=256, BOT=256, FFN=2048
// dk = KD/NH = 16, dv = VD/NH = 32, Mtot = L + HW = 4224 = 33*128

__device__ __forceinline__ float gelu_f(float x) {
    return 0.5f * x * (1.0f + erff(x * 0.70710678118654752f));
}

// ---------------- scratch (device globals; no allocation allowed) ----------------
__device__ float g_pixel_space[8 * 256 * 4096];   // (N,BOT,HW)
__device__ float g_pixel_kv  [8 * 384 * 4096];    // (N,KD+VD,HW)
__device__ float g_query_space[8 * 256 * 128];    // (N,BOT,L)
__device__ float g_query_qkv [8 * 512 * 128];     // (N,2KD+VD,L)
__device__ float g_ret       [8 * 256 * 128];     // gelu(bn(ret))
__device__ float g_qf        [8 * 256 * 128];
__device__ float g_ffn       [8 * 2048 * 128];

// =======================================================================
// SGEMM A: 64(o) x 64(j) block tile, 4x4 micro-tile, K-tile 16 (small GEMMs)
// Y[z][o][j] = EPI( sum_c W[o][c] * gx(X[z][c][j]) )
// GX: 1 -> gelu on X load
// EPI: 0 -> v*s+b ; 1 -> gelu(v*s+b) ; 2 -> gelu(res + v*s+b)
// =======================================================================
template<int GX, int EPI>
__global__ void __launch_bounds__(256) gemm_bn(
    const float* __restrict__ W, const float* __restrict__ X,
    const float* __restrict__ sc, const float* __restrict__ bi,
    const float* __restrict__ res, float* __restrict__ Y,
    int M, int K, int J)
{
    __shared__ float Ws[16][64];
    __shared__ float Xs[16][68];

    const int tx = threadIdx.x, ty = threadIdx.y;
    const int tid = ty * 16 + tx;
    const int o0 = blockIdx.x * 64, j0 = blockIdx.y * 64;
    const long z = blockIdx.z;

    X += z * (long)K * J;
    Y += z * (long)M * J;
    if (EPI == 2) res += z * (long)M * J;

    const int lo  = tid >> 2;          // 0..63
    const int lk4 = (tid & 3) << 2;
    const int lkx = tid >> 4;          // 0..15
    const int lj4 = (tid & 15) << 2;
    const int ty4 = ty << 2, tx4 = tx << 2;

    float acc[4][4];
#pragma unroll
    for (int i = 0; i < 4; i++)
#pragma unroll
        for (int j = 0; j < 4; j++) acc[i][j] = 0.f;

    for (int k0 = 0; k0 < K; k0 += 16) {
        float4 wv = *(const float4*)(W + (long)(o0 + lo) * K + k0 + lk4);
        Ws[lk4 + 0][lo] = wv.x;
        Ws[lk4 + 1][lo] = wv.y;
        Ws[lk4 + 2][lo] = wv.z;
        Ws[lk4 + 3][lo] = wv.w;
        float4 xv = *(const float4*)(X + (long)(k0 + lkx) * J + j0 + lj4);
        if (GX) {
            xv.x = gelu_f(xv.x); xv.y = gelu_f(xv.y);
            xv.z = gelu_f(xv.z); xv.w = gelu_f(xv.w);
        }
        *(float4*)&Xs[lkx][lj4] = xv;
        __syncthreads();
#pragma unroll
        for (int kk = 0; kk < 16; kk++) {
            float4 a4 = *(const float4*)&Ws[kk][ty4];
            float4 b4 = *(const float4*)&Xs[kk][tx4];
            float a[4] = {a4.x, a4.y, a4.z, a4.w};
            float b[4] = {b4.x, b4.y, b4.z, b4.w};
#pragma unroll
            for (int i = 0; i < 4; i++)
#pragma unroll
                for (int j = 0; j < 4; j++) acc[i][j] += a[i] * b[j];
        }
        __syncthreads();
    }

#pragma unroll
    for (int i = 0; i < 4; i++) {
        int o = o0 + ty4 + i;
        float s = sc[o], b = bi[o];
        float vx[4];
#pragma unroll
        for (int j = 0; j < 4; j++) vx[j] = acc[i][j] * s + b;
        long base = (long)o * J + j0 + tx4;
        if (EPI == 1) {
#pragma unroll
            for (int j = 0; j < 4; j++) vx[j] = gelu_f(vx[j]);
        } else if (EPI == 2) {
            float4 r4 = *(const float4*)(res + base);
            vx[0] = gelu_f(r4.x + vx[0]);
            vx[1] = gelu_f(r4.y + vx[1]);
            vx[2] = gelu_f(r4.z + vx[2]);
            vx[3] = gelu_f(r4.w + vx[3]);
        }
        *(float4*)(Y + base) = make_float4(vx[0], vx[1], vx[2], vx[3]);
    }
}

// =======================================================================
// SGEMM B: 128(o) x 64(j) block tile, 8x4 micro-tile, K-tile 16 (big GEMMs)
// Same contract as gemm_bn. M must be multiple of 128.
// =======================================================================
template<int GX, int EPI>
__global__ void __launch_bounds__(256) gemm_bn_big(
    const float* __restrict__ W, const float* __restrict__ X,
    const float* __restrict__ sc, const float* __restrict__ bi,
    const float* __restrict__ res, float* __restrict__ Y,
    int M, int K, int J)
{
    __shared__ float Ws[16][128];
    __shared__ float Xs[16][68];

    const int tx = threadIdx.x, ty = threadIdx.y;   // 16 x 16
    const int tid = ty * 16 + tx;
    const int o0 = blockIdx.x * 128, j0 = blockIdx.y * 64;
    const long z = blockIdx.z;

    X += z * (long)K * J;
    Y += z * (long)M * J;
    if (EPI == 2) res += z * (long)M * J;

    // W load: 128x16 = 512 float4, 2 per thread
    const int wo0 = tid >> 2;            // 0..63
    const int wk4 = (tid & 3) << 2;      // 0,4,8,12
    // X load: 16x64 = 256 float4, 1 per thread
    const int lkx = tid >> 4;            // 0..15
    const int lj4 = (tid & 15) << 2;
    const int ty8 = ty << 3, tx4 = tx << 2;

    float acc[8][4];
#pragma unroll
    for (int i = 0; i < 8; i++)
#pragma unroll
        for (int j = 0; j < 4; j++) acc[i][j] = 0.f;

    for (int k0 = 0; k0 < K; k0 += 16) {
#pragma unroll
        for (int half = 0; half < 2; half++) {
            int o = wo0 + half * 64;
            float4 wv = *(const float4*)(W + (long)(o0 + o) * K + k0 + wk4);
            Ws[wk4 + 0][o] = wv.x;
            Ws[wk4 + 1][o] = wv.y;
            Ws[wk4 + 2][o] = wv.z;
            Ws[wk4 + 3][o] = wv.w;
        }
        float4 xv = *(const float4*)(X + (long)(k0 + lkx) * J + j0 + lj4);
        if (GX) {
            xv.x = gelu_f(xv.x); xv.y = gelu_f(xv.y);
            xv.z = gelu_f(xv.z); xv.w = gelu_f(xv.w);
        }
        *(float4*)&Xs[lkx][lj4] = xv;
        __syncthreads();
#pragma unroll
        for (int kk = 0; kk < 16; kk++) {
            float4 a0 = *(const float4*)&Ws[kk][ty8];
            float4 a1 = *(const float4*)&Ws[kk][ty8 + 4];
            float4 b4 = *(const float4*)&Xs[kk][tx4];
            float a[8] = {a0.x, a0.y, a0.z, a0.w, a1.x, a1.y, a1.z, a1.w};
            float b[4] = {b4.x, b4.y, b4.z, b4.w};
#pragma unroll
            for (int i = 0; i < 8; i++)
#pragma unroll
                for (int j = 0; j < 4; j++) acc[i][j] += a[i] * b[j];
        }
        __syncthreads();
    }

#pragma unroll
    for (int i = 0; i < 8; i++) {
        int o = o0 + ty8 + i;
        float s = sc[o], b = bi[o];
        float vx[4];
#pragma unroll
        for (int j = 0; j < 4; j++) vx[j] = acc[i][j] * s + b;
        long base = (long)o * J + j0 + tx4;
        if (EPI == 1) {
#pragma unroll
            for (int j = 0; j < 4; j++) vx[j] = gelu_f(vx[j]);
        } else if (EPI == 2) {
            float4 r4 = *(const float4*)(res + base);
            vx[0] = gelu_f(r4.x + vx[0]);
            vx[1] = gelu_f(r4.y + vx[1]);
            vx[2] = gelu_f(r4.z + vx[2]);
            vx[3] = gelu_f(r4.w + vx[3]);
        }
        *(float4*)(Y + base) = make_float4(vx[0], vx[1], vx[2], vx[3]);
    }
}

// =======================================================================
// Fused attention. Block = (n, h, 32-row l chunk). Online softmax over 33
// m-tiles of 128 (tile 0 = query k/v from qkv, tiles 1..32 = pixel k/v).
// b_sim is per-head-constant -> cancels in softmax. Epilogue: gelu(bn(O/rowL)).
// =======================================================================
__global__ void __launch_bounds__(256) attn_kernel(
    const float* __restrict__ qkv,    // (8,512,128)
    const float* __restrict__ pkv,    // (8,384,4096)
    const float* __restrict__ s_sim,
    const float* __restrict__ s_ret_, const float* __restrict__ b_ret_,
    float* __restrict__ ret)          // (8,256,128)
{
    const int lc = blockIdx.x;    // 0..3
    const int h  = blockIdx.y;    // 0..7
    const int n  = blockIdx.z;    // 0..7
    const int l0 = lc * 32;
    const int tid  = threadIdx.x;
    const int w    = tid >> 5;
    const int lane = tid & 31;

    __shared__ float Qs[16][32];
    __shared__ float Ks[16][128];
    __shared__ float Vs[32][128];
    __shared__ float Ps[32][129];
    __shared__ float red1[8][33];
    __shared__ float red2[8][33];
    __shared__ float rowM[32], rowL[32], alphaS[32];

    {
        const float* qbase = qkv + ((long)n * 512 + h * 16) * 128;
        for (int i = tid; i < 16 * 32; i += 256) {
            int d = i >> 5, r = i & 31;
            Qs[d][r] = qbase[d * 128 + l0 + r];
        }
    }
    if (tid < 32) { rowM[tid] = -1e30f; rowL[tid] = 0.f; }
    const float sscale = s_sim[h];
    float acc[4] = {0.f, 0.f, 0.f, 0.f};
    const int m0 = w * 16;
    const int dbase = w * 4;
    __syncthreads();

    for (int t = 0; t < 33; t++) {
        const float* ksrc; const float* vsrc; long rs;
        if (t == 0) {
            ksrc = qkv + ((long)n * 512 + 128 + h * 16) * 128;
            vsrc = qkv + ((long)n * 512 + 256 + h * 32) * 128;
            rs = 128;
        } else {
            long off = (long)(t - 1) * 128;
            ksrc = pkv + ((long)n * 384 + h * 16) * 4096 + off;
            vsrc = pkv + ((long)n * 384 + 128 + h * 32) * 4096 + off;
            rs = 4096;
        }
        for (int i = tid; i < 512; i += 256) {
            int d = i >> 5, m = (i & 31) << 2;
            *(float4*)&Ks[d][m] = *(const float4*)(ksrc + (long)d * rs + m);
        }
        for (int i = tid; i < 1024; i += 256) {
            int d = i >> 5, m = (i & 31) << 2;
            *(float4*)&Vs[d][m] = *(const float4*)(vsrc + (long)d * rs + m);
        }
        __syncthreads();

        float sv[16];
#pragma unroll
        for (int j = 0; j < 16; j++) sv[j] = 0.f;
#pragma unroll
        for (int d = 0; d < 16; d++) {
            float qd = Qs[d][lane];
#pragma unroll
            for (int j4 = 0; j4 < 16; j4 += 4) {
                float4 kv = *(const float4*)&Ks[d][m0 + j4];
                sv[j4 + 0] += qd * kv.x;
                sv[j4 + 1] += qd * kv.y;
                sv[j4 + 2] += qd * kv.z;
                sv[j4 + 3] += qd * kv.w;
            }
        }
        float lm = -1e30f;
#pragma unroll
        for (int j = 0; j < 16; j++) { sv[j] *= sscale; lm = fmaxf(lm, sv[j]); }
        red1[w][lane] = lm;
        __syncthreads();

        float Mnew = rowM[lane];
#pragma unroll
        for (int ww = 0; ww < 8; ww++) Mnew = fmaxf(Mnew, red1[ww][lane]);

        float ls = 0.f;
#pragma unroll
        for (int j = 0; j < 16; j++) {
            float p = __expf(sv[j] - Mnew);
            Ps[lane][m0 + j] = p;
            ls += p;
        }
        red2[w][lane] = ls;
        __syncthreads();

        if (w == 0) {
            float ts = 0.f;
#pragma unroll
            for (int ww = 0; ww < 8; ww++) ts += red2[ww][lane];
            float alpha = __expf(rowM[lane] - Mnew);
            rowL[lane] = rowL[lane] * alpha + ts;
            rowM[lane] = Mnew;
            alphaS[lane] = alpha;
        }
        __syncthreads();

        float alpha = alphaS[lane];
#pragma unroll
        for (int jj = 0; jj < 4; jj++) acc[jj] *= alpha;
        for (int m4 = 0; m4 < 128; m4 += 4) {
            float p0 = Ps[lane][m4 + 0];
            float p1 = Ps[lane][m4 + 1];
            float p2 = Ps[lane][m4 + 2];
            float p3 = Ps[lane][m4 + 3];
#pragma unroll
            for (int jj = 0; jj < 4; jj++) {
                float4 v4 = *(const float4*)&Vs[dbase + jj][m4];
                acc[jj] += p0 * v4.x + p1 * v4.y + p2 * v4.z + p3 * v4.w;
            }
        }
        __syncthreads();
    }

    float inv = 1.f / rowL[lane];
#pragma unroll
    for (int jj = 0; jj < 4; jj++) {
        int d = dbase + jj;
        int c = h * 32 + d;
        float v = acc[jj] * inv;
        v = v * s_ret_[c] + b_ret_[c];
        ret[((long)n * 256 + c) * 128 + l0 + lane] = gelu_f(v);
    }
}

// ---------------- launch ----------------
extern "C" void kernel_launch(void* const* d_in, const int* in_sizes, int n_in,
                              void* d_out, int out_size)
{
    (void)in_sizes; (void)n_in; (void)out_size;
    const float* pixel = (const float*)d_in[0];
    const float* query = (const float*)d_in[1];
    const float* w_q1  = (const float*)d_in[2];
    const float* s_q1  = (const float*)d_in[3];
    const float* b_q1  = (const float*)d_in[4];
    const float* w_p1  = (const float*)d_in[5];
    const float* s_p1  = (const float*)d_in[6];
    const float* b_p1  = (const float*)d_in[7];
    const float* w_qkv = (const float*)d_in[8];
    const float* s_qkv = (const float*)d_in[9];
    const float* b_qkv = (const float*)d_in[10];
    const float* w_pkv = (const float*)d_in[11];
    const float* s_pkv = (const float*)d_in[12];
    const float* b_pkv = (const float*)d_in[13];
    const float* s_sim = (const float*)d_in[14];
    /* b_sim (d_in[15]) shifts every softmax row uniformly -> cancels exactly */
    const float* s_ret = (const float*)d_in[16];
    const float* b_ret = (const float*)d_in[17];
    const float* w_c3  = (const float*)d_in[18];
    const float* s_c3  = (const float*)d_in[19];
    const float* b_c3  = (const float*)d_in[20];
    const float* w_f1  = (const float*)d_in[21];
    const float* s_f1  = (const float*)d_in[22];
    const float* b_f1  = (const float*)d_in[23];
    const float* w_f2  = (const float*)d_in[24];
    const float* s_f2  = (const float*)d_in[25];
    const float* b_f2  = (const float*)d_in[26];

    float *ps, *pkv, *qs, *qkv, *ret, *qf, *ffn;
    cudaGetSymbolAddress((void**)&ps,  g_pixel_space);
    cudaGetSymbolAddress((void**)&pkv, g_pixel_kv);
    cudaGetSymbolAddress((void**)&qs,  g_query_space);
    cudaGetSymbolAddress((void**)&qkv, g_query_qkv);
    cudaGetSymbolAddress((void**)&ret, g_ret);
    cudaGetSymbolAddress((void**)&qf,  g_qf);
    cudaGetSymbolAddress((void**)&ffn, g_ffn);

    dim3 blk(16, 16);

    // pixel_space = gelu(bn(w_p1 @ gelu(pixel)))      M=256 K=2048 J=4096
    gemm_bn_big<1, 1><<<dim3(2, 64, 8), blk>>>(w_p1, pixel, s_p1, b_p1, nullptr, ps, 256, 2048, 4096);
    // query_space = gelu(bn(w_q1 @ query))            M=256 K=256  J=128
    gemm_bn<0, 1><<<dim3(4, 2, 8), blk>>>(w_q1, query, s_q1, b_q1, nullptr, qs, 256, 256, 128);
    // pixel_kv = bn(w_pkv @ pixel_space)              M=384 K=256  J=4096
    gemm_bn_big<0, 0><<<dim3(3, 64, 8), blk>>>(w_pkv, ps, s_pkv, b_pkv, nullptr, pkv, 384, 256, 4096);
    // query_qkv = bn(w_qkv @ query_space)             M=512 K=256  J=128
    gemm_bn<0, 0><<<dim3(8, 2, 8), blk>>>(w_qkv, qs, s_qkv, b_qkv, nullptr, qkv, 512, 256, 128);
    // fused attention -> g_ret
    attn_kernel<<<dim3(4, 8, 8), 256>>>(qkv, pkv, s_sim, s_ret, b_ret, ret);
    // qf = gelu(query + bn(w_c3 @ ret))               M=256 K=256  J=128
    gemm_bn<0, 2><<<dim3(4, 2, 8), blk>>>(w_c3, ret, s_c3, b_c3, query, qf, 256, 256, 128);
    // ffn = gelu(bn(w_f1 @ qf))                       M=2048 K=256 J=128
    gemm_bn_big<0, 1><<<dim3(16, 2, 8), blk>>>(w_f1, qf, s_f1, b_f1, nullptr, ffn, 2048, 256, 128);
    // out = gelu(qf + bn(w_f2 @ ffn))                 M=256 K=2048 J=128
    gemm_bn<0, 2><<<dim3(4, 2, 8), blk>>>(w_f2, ffn, s_f2, b_f2, qf, (float*)d_out, 256, 2048, 128);
}

// round 6
// speedup vs baseline: 1.6573x; 1.6573x over previous
#include <cuda_runtime.h>
#include <math.h>
#include <stdint.h>

// Shapes: N=8, Cp=2048, HW=4096, Cq=256, L=128, NH=8, KD=128, VD=256, BOT=256, FFN=2048

__device__ __forceinline__ float gelu_f(float x) {
    return 0.5f * x * (1.0f + erff(x * 0.70710678118654752f));
}
// cvt.rna.tf32 destination must be a .b32 register -> use "=r" constraint.
__device__ __forceinline__ float to_tf32(float x) {
    uint32_t r; asm("cvt.rna.tf32.f32 %0, %1;" : "=r"(r) : "f"(x));
    return __uint_as_float(r);
}

// ---------------- scratch (device globals; no allocation allowed) ----------------
__device__ float g_pixel_space[8 * 256 * 4096];   // (N,BOT,HW)
__device__ float g_pixel_kv  [8 * 384 * 4096];    // (N,KD+VD,HW)
__device__ float g_query_space[8 * 256 * 128];
__device__ float g_query_qkv [8 * 512 * 128];
__device__ float g_ret       [8 * 256 * 128];
__device__ float g_qf        [8 * 256 * 128];
__device__ float g_ffn       [8 * 2048 * 128];

// =======================================================================
// tf32 mma.sync GEMM (sm_80+ path; compiles for plain sm_100 target).
// Y[z][o][j] = EPI( sum_c W[o][c] * gx(X[z][c][j]) )
//   GX:  1 -> gelu applied to X during smem staging
//   EPI: 0 -> v*s+b ; 1 -> gelu(v*s+b) ; 2 -> gelu(res + v*s+b)
// CTA tile 128(M) x 128(N), K-chunk 16. 8 warps: warp grid 2(M) x 4(N),
// warp tile 64x32 via mma.m16n8k8: 4 m-frags x 4 n-frags.
// M % 128 == 0, J % 128 == 0, K % 16 == 0 (all shapes here satisfy this).
// Operands rounded to tf32 with cvt.rna during staging (unbiased).
// =======================================================================
template<int GX, int EPI>
__global__ void __launch_bounds__(256) mma_gemm(
    const float* __restrict__ W, const float* __restrict__ X,
    const float* __restrict__ sc, const float* __restrict__ bi,
    const float* __restrict__ res, float* __restrict__ Y,
    int M, int K, int J)
{
    __shared__ float As[128 * 20];    // A[m][k], row stride 20 (16 + 4 pad)
    __shared__ float Bs[16 * 136];    // B[k][n], row stride 136 (128 + 8 pad)

    const int tid = threadIdx.x;
    const int wid = tid >> 5, lane = tid & 31;
    const int grp = lane >> 2, tig = lane & 3;
    const int wm = wid & 1, wn = wid >> 1;          // warp_m in {0,1}, warp_n in {0..3}
    const int o0 = blockIdx.y * 128, j0 = blockIdx.x * 128;
    const long z = blockIdx.z;

    X += z * (long)K * J;
    Y += z * (long)M * J;
    if (EPI == 2) res += z * (long)M * J;

    float c[4][4][4] = {};

    const int ar = tid >> 2;           // 0..63 (A staging row base)
    const int af = (tid & 3) * 4;      // 0,4,8,12
    const int bk = tid >> 4;           // 0..15 (B staging row)
    const int bn = (tid & 15) * 8;     // 0..120

    for (int k0 = 0; k0 < K; k0 += 16) {
        // ---- stage A tile: 128 x 16 (tf32-rounded weights) ----
#pragma unroll
        for (int h = 0; h < 2; h++) {
            int r = ar + h * 64;
            float4 v = *(const float4*)(W + (long)(o0 + r) * K + k0 + af);
            *(float4*)&As[r * 20 + af] =
                make_float4(to_tf32(v.x), to_tf32(v.y), to_tf32(v.z), to_tf32(v.w));
        }
        // ---- stage B tile: 16 x 128 (optional gelu, tf32-rounded) ----
#pragma unroll
        for (int h = 0; h < 2; h++) {
            float4 v = *(const float4*)(X + (long)(k0 + bk) * J + j0 + bn + h * 4);
            if (GX) {
                v.x = gelu_f(v.x); v.y = gelu_f(v.y);
                v.z = gelu_f(v.z); v.w = gelu_f(v.w);
            }
            *(float4*)&Bs[bk * 136 + bn + h * 4] =
                make_float4(to_tf32(v.x), to_tf32(v.y), to_tf32(v.z), to_tf32(v.w));
        }
        __syncthreads();

        // ---- 2 x k8 mma steps ----
#pragma unroll
        for (int kk = 0; kk < 16; kk += 8) {
            uint32_t a[4][4], b[4][2];
#pragma unroll
            for (int mt = 0; mt < 4; mt++) {
                int rm = wm * 64 + mt * 16 + grp;
                a[mt][0] = __float_as_uint(As[rm * 20 + kk + tig]);
                a[mt][1] = __float_as_uint(As[(rm + 8) * 20 + kk + tig]);
                a[mt][2] = __float_as_uint(As[rm * 20 + kk + tig + 4]);
                a[mt][3] = __float_as_uint(As[(rm + 8) * 20 + kk + tig + 4]);
            }
#pragma unroll
            for (int nt = 0; nt < 4; nt++) {
                int nb = wn * 32 + nt * 8 + grp;
                b[nt][0] = __float_as_uint(Bs[(kk + tig) * 136 + nb]);
                b[nt][1] = __float_as_uint(Bs[(kk + tig + 4) * 136 + nb]);
            }
#pragma unroll
            for (int mt = 0; mt < 4; mt++)
#pragma unroll
                for (int nt = 0; nt < 4; nt++)
                    asm volatile(
                        "mma.sync.aligned.m16n8k8.row.col.f32.tf32.tf32.f32 "
                        "{%0,%1,%2,%3}, {%4,%5,%6,%7}, {%8,%9}, {%0,%1,%2,%3};\n"
                        : "+f"(c[mt][nt][0]), "+f"(c[mt][nt][1]),
                          "+f"(c[mt][nt][2]), "+f"(c[mt][nt][3])
                        : "r"(a[mt][0]), "r"(a[mt][1]), "r"(a[mt][2]), "r"(a[mt][3]),
                          "r"(b[nt][0]), "r"(b[nt][1]));
        }
        __syncthreads();
    }

    // ---- epilogue ----
    // c0:(grp, 2tig) c1:(grp, 2tig+1) c2:(grp+8, 2tig) c3:(grp+8, 2tig+1)
#pragma unroll
    for (int mt = 0; mt < 4; mt++) {
#pragma unroll
        for (int half = 0; half < 2; half++) {
            int o = o0 + wm * 64 + mt * 16 + grp + half * 8;
            float s = sc[o], bb = bi[o];
#pragma unroll
            for (int nt = 0; nt < 4; nt++) {
                int j = j0 + wn * 32 + nt * 8 + tig * 2;
                float v0 = c[mt][nt][half * 2 + 0] * s + bb;
                float v1 = c[mt][nt][half * 2 + 1] * s + bb;
                long base = (long)o * J + j;
                if (EPI == 1) {
                    v0 = gelu_f(v0); v1 = gelu_f(v1);
                } else if (EPI == 2) {
                    float2 r2 = *(const float2*)(res + base);
                    v0 = gelu_f(r2.x + v0);
                    v1 = gelu_f(r2.y + v1);
                }
                *(float2*)(Y + base) = make_float2(v0, v1);
            }
        }
    }
}

// =======================================================================
// fused attention (unchanged — passed in R2). Block=(n,h,32-l-chunk),
// online softmax over 33 m-tiles (tile 0 = query kv, 1..32 = pixel kv).
// b_sim per-head constant -> cancels in softmax. Epilogue gelu(bn(O/rowL)).
// =======================================================================
__global__ void __launch_bounds__(256) attn_kernel(
    const float* __restrict__ qkv, const float* __restrict__ pkv,
    const float* __restrict__ s_sim,
    const float* __restrict__ s_ret_, const float* __restrict__ b_ret_,
    float* __restrict__ ret)
{
    const int lc = blockIdx.x, h = blockIdx.y, n = blockIdx.z;
    const int l0 = lc * 32;
    const int tid = threadIdx.x, w = tid >> 5, lane = tid & 31;
    __shared__ float Qs[16][32];
    __shared__ float Ks[16][128];
    __shared__ float Vs[32][128];
    __shared__ float Ps[32][129];
    __shared__ float red1[8][33];
    __shared__ float red2[8][33];
    __shared__ float rowM[32], rowL[32], alphaS[32];
    {
        const float* qbase = qkv + ((long)n * 512 + h * 16) * 128;
        for (int i = tid; i < 16 * 32; i += 256) {
            int d = i >> 5, r = i & 31;
            Qs[d][r] = qbase[d * 128 + l0 + r];
        }
    }
    if (tid < 32) { rowM[tid] = -1e30f; rowL[tid] = 0.f; }
    const float sscale = s_sim[h];
    float acc[4] = {0.f, 0.f, 0.f, 0.f};
    const int m0 = w * 16, dbase = w * 4;
    __syncthreads();
    for (int t = 0; t < 33; t++) {
        const float* ksrc; const float* vsrc; long rs;
        if (t == 0) {
            ksrc = qkv + ((long)n * 512 + 128 + h * 16) * 128;
            vsrc = qkv + ((long)n * 512 + 256 + h * 32) * 128;
            rs = 128;
        } else {
            long off = (long)(t - 1) * 128;
            ksrc = pkv + ((long)n * 384 + h * 16) * 4096 + off;
            vsrc = pkv + ((long)n * 384 + 128 + h * 32) * 4096 + off;
            rs = 4096;
        }
        for (int i = tid; i < 512; i += 256) {
            int d = i >> 5, m = (i & 31) << 2;
            *(float4*)&Ks[d][m] = *(const float4*)(ksrc + (long)d * rs + m);
        }
        for (int i = tid; i < 1024; i += 256) {
            int d = i >> 5, m = (i & 31) << 2;
            *(float4*)&Vs[d][m] = *(const float4*)(vsrc + (long)d * rs + m);
        }
        __syncthreads();
        float sv[16];
#pragma unroll
        for (int j = 0; j < 16; j++) sv[j] = 0.f;
#pragma unroll
        for (int d = 0; d < 16; d++) {
            float qd = Qs[d][lane];
#pragma unroll
            for (int j4 = 0; j4 < 16; j4 += 4) {
                float4 kv = *(const float4*)&Ks[d][m0 + j4];
                sv[j4 + 0] += qd * kv.x; sv[j4 + 1] += qd * kv.y;
                sv[j4 + 2] += qd * kv.z; sv[j4 + 3] += qd * kv.w;
            }
        }
        float lm = -1e30f;
#pragma unroll
        for (int j = 0; j < 16; j++) { sv[j] *= sscale; lm = fmaxf(lm, sv[j]); }
        red1[w][lane] = lm;
        __syncthreads();
        float Mnew = rowM[lane];
#pragma unroll
        for (int ww = 0; ww < 8; ww++) Mnew = fmaxf(Mnew, red1[ww][lane]);
        float ls = 0.f;
#pragma unroll
        for (int j = 0; j < 16; j++) {
            float p = __expf(sv[j] - Mnew);
            Ps[lane][m0 + j] = p;
            ls += p;
        }
        red2[w][lane] = ls;
        __syncthreads();
        if (w == 0) {
            float ts = 0.f;
#pragma unroll
            for (int ww = 0; ww < 8; ww++) ts += red2[ww][lane];
            float alpha = __expf(rowM[lane] - Mnew);
            rowL[lane] = rowL[lane] * alpha + ts;
            rowM[lane] = Mnew;
            alphaS[lane] = alpha;
        }
        __syncthreads();
        float alpha = alphaS[lane];
#pragma unroll
        for (int jj = 0; jj < 4; jj++) acc[jj] *= alpha;
        for (int m4 = 0; m4 < 128; m4 += 4) {
            float p0 = Ps[lane][m4 + 0], p1 = Ps[lane][m4 + 1];
            float p2 = Ps[lane][m4 + 2], p3 = Ps[lane][m4 + 3];
#pragma unroll
            for (int jj = 0; jj < 4; jj++) {
                float4 v4 = *(const float4*)&Vs[dbase + jj][m4];
                acc[jj] += p0 * v4.x + p1 * v4.y + p2 * v4.z + p3 * v4.w;
            }
        }
        __syncthreads();
    }
    float inv = 1.f / rowL[lane];
#pragma unroll
    for (int jj = 0; jj < 4; jj++) {
        int d = dbase + jj;
        int c = h * 32 + d;
        float v = acc[jj] * inv;
        v = v * s_ret_[c] + b_ret_[c];
        ret[((long)n * 256 + c) * 128 + l0 + lane] = gelu_f(v);
    }
}

// ---------------- launch ----------------
extern "C" void kernel_launch(void* const* d_in, const int* in_sizes, int n_in,
                              void* d_out, int out_size)
{
    (void)in_sizes; (void)n_in; (void)out_size;
    const float* pixel = (const float*)d_in[0];
    const float* query = (const float*)d_in[1];
    const float* w_q1  = (const float*)d_in[2];
    const float* s_q1  = (const float*)d_in[3];
    const float* b_q1  = (const float*)d_in[4];
    const float* w_p1  = (const float*)d_in[5];
    const float* s_p1  = (const float*)d_in[6];
    const float* b_p1  = (const float*)d_in[7];
    const float* w_qkv = (const float*)d_in[8];
    const float* s_qkv = (const float*)d_in[9];
    const float* b_qkv = (const float*)d_in[10];
    const float* w_pkv = (const float*)d_in[11];
    const float* s_pkv = (const float*)d_in[12];
    const float* b_pkv = (const float*)d_in[13];
    const float* s_sim = (const float*)d_in[14];
    /* b_sim (d_in[15]) is per-head constant -> cancels in softmax */
    const float* s_ret = (const float*)d_in[16];
    const float* b_ret = (const float*)d_in[17];
    const float* w_c3  = (const float*)d_in[18];
    const float* s_c3  = (const float*)d_in[19];
    const float* b_c3  = (const float*)d_in[20];
    const float* w_f1  = (const float*)d_in[21];
    const float* s_f1  = (const float*)d_in[22];
    const float* b_f1  = (const float*)d_in[23];
    const float* w_f2  = (const float*)d_in[24];
    const float* s_f2  = (const float*)d_in[25];
    const float* b_f2  = (const float*)d_in[26];

    float *ps, *pkv, *qs, *qkv, *ret, *qf, *ffn;
    cudaGetSymbolAddress((void**)&ps,  g_pixel_space);
    cudaGetSymbolAddress((void**)&pkv, g_pixel_kv);
    cudaGetSymbolAddress((void**)&qs,  g_query_space);
    cudaGetSymbolAddress((void**)&qkv, g_query_qkv);
    cudaGetSymbolAddress((void**)&ret, g_ret);
    cudaGetSymbolAddress((void**)&qf,  g_qf);
    cudaGetSymbolAddress((void**)&ffn, g_ffn);

    // pixel_space = gelu(bn(w_p1 @ gelu(pixel)))      M=256 K=2048 J=4096
    mma_gemm<1, 1><<<dim3(32, 2, 8), 256>>>(w_p1, pixel, s_p1, b_p1, nullptr, ps, 256, 2048, 4096);
    // query_space = gelu(bn(w_q1 @ query))            M=256 K=256  J=128
    mma_gemm<0, 1><<<dim3(1, 2, 8), 256>>>(w_q1, query, s_q1, b_q1, nullptr, qs, 256, 256, 128);
    // pixel_kv = bn(w_pkv @ pixel_space)              M=384 K=256  J=4096
    mma_gemm<0, 0><<<dim3(32, 3, 8), 256>>>(w_pkv, ps, s_pkv, b_pkv, nullptr, pkv, 384, 256, 4096);
    // query_qkv = bn(w_qkv @ query_space)             M=512 K=256  J=128
    mma_gemm<0, 0><<<dim3(1, 4, 8), 256>>>(w_qkv, qs, s_qkv, b_qkv, nullptr, qkv, 512, 256, 128);
    // fused attention -> g_ret
    attn_kernel<<<dim3(4, 8, 8), 256>>>(qkv, pkv, s_sim, s_ret, b_ret, ret);
    // qf = gelu(query + bn(w_c3 @ ret))               M=256 K=256  J=128
    mma_gemm<0, 2><<<dim3(1, 2, 8), 256>>>(w_c3, ret, s_c3, b_c3, query, qf, 256, 256, 128);
    // ffn = gelu(bn(w_f1 @ qf))                       M=2048 K=256 J=128
    mma_gemm<0, 1><<<dim3(1, 16, 8), 256>>>(w_f1, qf, s_f1, b_f1, nullptr, ffn, 2048, 256, 128);
    // out = gelu(qf + bn(w_f2 @ ffn))                 M=256 K=2048 J=128
    mma_gemm<0, 2><<<dim3(1, 2, 8), 256>>>(w_f2, ffn, s_f2, b_f2, qf, (float*)d_out, 256, 2048, 128);
}

// round 9
// speedup vs baseline: 1.8285x; 1.1033x over previous
#include <cuda_runtime.h>
#include <math.h>
#include <stdint.h>

// Shapes: N=8, Cp=2048, HW=4096, Cq=256, L=128, NH=8, KD=128, VD=256, BOT=256, FFN=2048

__device__ __forceinline__ float gelu_f(float x) {
    return 0.5f * x * (1.0f + erff(x * 0.70710678118654752f));
}
// cvt.rna.tf32 destination must be a .b32 register -> "=r" constraint.
__device__ __forceinline__ float to_tf32(float x) {
    uint32_t r; asm("cvt.rna.tf32.f32 %0, %1;" : "=r"(r) : "f"(x));
    return __uint_as_float(r);
}
__device__ __forceinline__ float4 tf32_4(float4 v) {
    return make_float4(to_tf32(v.x), to_tf32(v.y), to_tf32(v.z), to_tf32(v.w));
}

// ---------------- scratch (device globals; no allocation allowed) ----------------
__device__ float g_pixel_space[8 * 256 * 4096];   // (N,BOT,HW)
__device__ float g_pixel_kv  [8 * 384 * 4096];    // (N,KD+VD,HW)
__device__ float g_query_space[8 * 256 * 128];
__device__ float g_query_qkv [8 * 512 * 128];
__device__ float g_ret       [8 * 256 * 128];
__device__ float g_qf        [8 * 256 * 128];
__device__ float g_ffn       [8 * 2048 * 128];

// =======================================================================
// tf32 mma.sync GEMM, depth-2 software pipeline.
// Y[z][o][j] = EPI( sum_c W[o][c] * gx(X[z][c][j]) )
//   GX:  1 -> gelu applied to X during reg->smem staging
//   EPI: 0 -> v*s+b ; 1 -> gelu(v*s+b) ; 2 -> gelu(res + v*s+b)
// CTA tile 128(M) x 128(N), K-chunk 16, double-buffered smem.
// While MMAs consume buffer s&1, gmem loads for chunk s+1 are in flight in
// registers; committed to buffer (s+1)&1 before the single per-chunk sync.
// 8 warps: warp grid 2(M) x 4(N), warp tile 64x32 via mma.m16n8k8.
// Requires M%128==0, J%128==0, K%16==0 (all shapes here comply).
// =======================================================================
template<int GX, int EPI>
__global__ void __launch_bounds__(256) mma_gemm(
    const float* __restrict__ W, const float* __restrict__ X,
    const float* __restrict__ sc, const float* __restrict__ bi,
    const float* __restrict__ res, float* __restrict__ Y,
    int M, int K, int J)
{
    __shared__ float As[2][128 * 20];   // A[m][k], row stride 20 (16 + 4 pad)
    __shared__ float Bs[2][16 * 136];   // B[k][n], row stride 136 (128 + 8 pad)

    const int tid = threadIdx.x;
    const int wid = tid >> 5, lane = tid & 31;
    const int grp = lane >> 2, tig = lane & 3;
    const int wm = wid & 1, wn = wid >> 1;          // warp_m {0,1}, warp_n {0..3}
    const int o0 = blockIdx.y * 128, j0 = blockIdx.x * 128;
    const long z = blockIdx.z;

    X += z * (long)K * J;
    Y += z * (long)M * J;
    if (EPI == 2) res += z * (long)M * J;

    float c[4][4][4] = {};

    const int ar = tid >> 2;           // 0..63 (A staging row base)
    const int af = (tid & 3) * 4;      // 0,4,8,12
    const int bk = tid >> 4;           // 0..15 (B staging row)
    const int bn = (tid & 15) * 8;     // 0..120

    float4 pa0, pa1, pb0, pb1;         // prefetch registers

    auto gload = [&](int k0) {
        pa0 = *(const float4*)(W + (long)(o0 + ar) * K + k0 + af);
        pa1 = *(const float4*)(W + (long)(o0 + ar + 64) * K + k0 + af);
        pb0 = *(const float4*)(X + (long)(k0 + bk) * J + j0 + bn);
        pb1 = *(const float4*)(X + (long)(k0 + bk) * J + j0 + bn + 4);
    };
    auto sstore = [&](int buf) {
        *(float4*)&As[buf][ar * 20 + af]        = tf32_4(pa0);
        *(float4*)&As[buf][(ar + 64) * 20 + af] = tf32_4(pa1);
        float4 v0 = pb0, v1 = pb1;
        if (GX) {
            v0.x = gelu_f(v0.x); v0.y = gelu_f(v0.y);
            v0.z = gelu_f(v0.z); v0.w = gelu_f(v0.w);
            v1.x = gelu_f(v1.x); v1.y = gelu_f(v1.y);
            v1.z = gelu_f(v1.z); v1.w = gelu_f(v1.w);
        }
        *(float4*)&Bs[buf][bk * 136 + bn]     = tf32_4(v0);
        *(float4*)&Bs[buf][bk * 136 + bn + 4] = tf32_4(v1);
    };

    gload(0);
    sstore(0);
    __syncthreads();

    const int nch = K >> 4;
    for (int s = 0; s < nch; s++) {
        const int cur = s & 1;
        if (s + 1 < nch) gload((s + 1) << 4);   // LDGs overlap MMAs below

#pragma unroll
        for (int kk = 0; kk < 16; kk += 8) {
            uint32_t a[4][4], b[4][2];
#pragma unroll
            for (int mt = 0; mt < 4; mt++) {
                int rm = wm * 64 + mt * 16 + grp;
                a[mt][0] = __float_as_uint(As[cur][rm * 20 + kk + tig]);
                a[mt][1] = __float_as_uint(As[cur][(rm + 8) * 20 + kk + tig]);
                a[mt][2] = __float_as_uint(As[cur][rm * 20 + kk + tig + 4]);
                a[mt][3] = __float_as_uint(As[cur][(rm + 8) * 20 + kk + tig + 4]);
            }
#pragma unroll
            for (int nt = 0; nt < 4; nt++) {
                int nb = wn * 32 + nt * 8 + grp;
                b[nt][0] = __float_as_uint(Bs[cur][(kk + tig) * 136 + nb]);
                b[nt][1] = __float_as_uint(Bs[cur][(kk + tig + 4) * 136 + nb]);
            }
#pragma unroll
            for (int mt = 0; mt < 4; mt++)
#pragma unroll
                for (int nt = 0; nt < 4; nt++)
                    asm volatile(
                        "mma.sync.aligned.m16n8k8.row.col.f32.tf32.tf32.f32 "
                        "{%0,%1,%2,%3}, {%4,%5,%6,%7}, {%8,%9}, {%0,%1,%2,%3};\n"
                        : "+f"(c[mt][nt][0]), "+f"(c[mt][nt][1]),
                          "+f"(c[mt][nt][2]), "+f"(c[mt][nt][3])
                        : "r"(a[mt][0]), "r"(a[mt][1]), "r"(a[mt][2]), "r"(a[mt][3]),
                          "r"(b[nt][0]), "r"(b[nt][1]));
        }

        if (s + 1 < nch) sstore(cur ^ 1);       // waits on LDGs; MMAs above covered them
        __syncthreads();
    }

    // ---- epilogue ----
    // c0:(grp, 2tig) c1:(grp, 2tig+1) c2:(grp+8, 2tig) c3:(grp+8, 2tig+1)
#pragma unroll
    for (int mt = 0; mt < 4; mt++) {
#pragma unroll
        for (int half = 0; half < 2; half++) {
            int o = o0 + wm * 64 + mt * 16 + grp + half * 8;
            float s = sc[o], bb = bi[o];
#pragma unroll
            for (int nt = 0; nt < 4; nt++) {
                int j = j0 + wn * 32 + nt * 8 + tig * 2;
                float v0 = c[mt][nt][half * 2 + 0] * s + bb;
                float v1 = c[mt][nt][half * 2 + 1] * s + bb;
                long base = (long)o * J + j;
                if (EPI == 1) {
                    v0 = gelu_f(v0); v1 = gelu_f(v1);
                } else if (EPI == 2) {
                    float2 r2 = *(const float2*)(res + base);
                    v0 = gelu_f(r2.x + v0);
                    v1 = gelu_f(r2.y + v1);
                }
                *(float2*)(Y + base) = make_float2(v0, v1);
            }
        }
    }
}

// =======================================================================
// fused attention (unchanged — passed in R2/R6). Block=(n,h,32-l-chunk),
// online softmax over 33 m-tiles (tile 0 = query kv, 1..32 = pixel kv).
// b_sim per-head constant -> cancels in softmax. Epilogue gelu(bn(O/rowL)).
// =======================================================================
__global__ void __launch_bounds__(256) attn_kernel(
    const float* __restrict__ qkv, const float* __restrict__ pkv,
    const float* __restrict__ s_sim,
    const float* __restrict__ s_ret_, const float* __restrict__ b_ret_,
    float* __restrict__ ret)
{
    const int lc = blockIdx.x, h = blockIdx.y, n = blockIdx.z;
    const int l0 = lc * 32;
    const int tid = threadIdx.x, w = tid >> 5, lane = tid & 31;
    __shared__ float Qs[16][32];
    __shared__ float Ks[16][128];
    __shared__ float Vs[32][128];
    __shared__ float Ps[32][129];
    __shared__ float red1[8][33];
    __shared__ float red2[8][33];
    __shared__ float rowM[32], rowL[32], alphaS[32];
    {
        const float* qbase = qkv + ((long)n * 512 + h * 16) * 128;
        for (int i = tid; i < 16 * 32; i += 256) {
            int d = i >> 5, r = i & 31;
            Qs[d][r] = qbase[d * 128 + l0 + r];
        }
    }
    if (tid < 32) { rowM[tid] = -1e30f; rowL[tid] = 0.f; }
    const float sscale = s_sim[h];
    float acc[4] = {0.f, 0.f, 0.f, 0.f};
    const int m0 = w * 16, dbase = w * 4;
    __syncthreads();
    for (int t = 0; t < 33; t++) {
        const float* ksrc; const float* vsrc; long rs;
        if (t == 0) {
            ksrc = qkv + ((long)n * 512 + 128 + h * 16) * 128;
            vsrc = qkv + ((long)n * 512 + 256 + h * 32) * 128;
            rs = 128;
        } else {
            long off = (long)(t - 1) * 128;
            ksrc = pkv + ((long)n * 384 + h * 16) * 4096 + off;
            vsrc = pkv + ((long)n * 384 + 128 + h * 32) * 4096 + off;
            rs = 4096;
        }
        for (int i = tid; i < 512; i += 256) {
            int d = i >> 5, m = (i & 31) << 2;
            *(float4*)&Ks[d][m] = *(const float4*)(ksrc + (long)d * rs + m);
        }
        for (int i = tid; i < 1024; i += 256) {
            int d = i >> 5, m = (i & 31) << 2;
            *(float4*)&Vs[d][m] = *(const float4*)(vsrc + (long)d * rs + m);
        }
        __syncthreads();
        float sv[16];
#pragma unroll
        for (int j = 0; j < 16; j++) sv[j] = 0.f;
#pragma unroll
        for (int d = 0; d < 16; d++) {
            float qd = Qs[d][lane];
#pragma unroll
            for (int j4 = 0; j4 < 16; j4 += 4) {
                float4 kv = *(const float4*)&Ks[d][m0 + j4];
                sv[j4 + 0] += qd * kv.x; sv[j4 + 1] += qd * kv.y;
                sv[j4 + 2] += qd * kv.z; sv[j4 + 3] += qd * kv.w;
            }
        }
        float lm = -1e30f;
#pragma unroll
        for (int j = 0; j < 16; j++) { sv[j] *= sscale; lm = fmaxf(lm, sv[j]); }
        red1[w][lane] = lm;
        __syncthreads();
        float Mnew = rowM[lane];
#pragma unroll
        for (int ww = 0; ww < 8; ww++) Mnew = fmaxf(Mnew, red1[ww][lane]);
        float ls = 0.f;
#pragma unroll
        for (int j = 0; j < 16; j++) {
            float p = __expf(sv[j] - Mnew);
            Ps[lane][m0 + j] = p;
            ls += p;
        }
        red2[w][lane] = ls;
        __syncthreads();
        if (w == 0) {
            float ts = 0.f;
#pragma unroll
            for (int ww = 0; ww < 8; ww++) ts += red2[ww][lane];
            float alpha = __expf(rowM[lane] - Mnew);
            rowL[lane] = rowL[lane] * alpha + ts;
            rowM[lane] = Mnew;
            alphaS[lane] = alpha;
        }
        __syncthreads();
        float alpha = alphaS[lane];
#pragma unroll
        for (int jj = 0; jj < 4; jj++) acc[jj] *= alpha;
        for (int m4 = 0; m4 < 128; m4 += 4) {
            float p0 = Ps[lane][m4 + 0], p1 = Ps[lane][m4 + 1];
            float p2 = Ps[lane][m4 + 2], p3 = Ps[lane][m4 + 3];
#pragma unroll
            for (int jj = 0; jj < 4; jj++) {
                float4 v4 = *(const float4*)&Vs[dbase + jj][m4];
                acc[jj] += p0 * v4.x + p1 * v4.y + p2 * v4.z + p3 * v4.w;
            }
        }
        __syncthreads();
    }
    float inv = 1.f / rowL[lane];
#pragma unroll
    for (int jj = 0; jj < 4; jj++) {
        int d = dbase + jj;
        int c = h * 32 + d;
        float v = acc[jj] * inv;
        v = v * s_ret_[c] + b_ret_[c];
        ret[((long)n * 256 + c) * 128 + l0 + lane] = gelu_f(v);
    }
}

// ---------------- launch ----------------
extern "C" void kernel_launch(void* const* d_in, const int* in_sizes, int n_in,
                              void* d_out, int out_size)
{
    (void)in_sizes; (void)n_in; (void)out_size;
    const float* pixel = (const float*)d_in[0];
    const float* query = (const float*)d_in[1];
    const float* w_q1  = (const float*)d_in[2];
    const float* s_q1  = (const float*)d_in[3];
    const float* b_q1  = (const float*)d_in[4];
    const float* w_p1  = (const float*)d_in[5];
    const float* s_p1  = (const float*)d_in[6];
    const float* b_p1  = (const float*)d_in[7];
    const float* w_qkv = (const float*)d_in[8];
    const float* s_qkv = (const float*)d_in[9];
    const float* b_qkv = (const float*)d_in[10];
    const float* w_pkv = (const float*)d_in[11];
    const float* s_pkv = (const float*)d_in[12];
    const float* b_pkv = (const float*)d_in[13];
    const float* s_sim = (const float*)d_in[14];
    /* b_sim (d_in[15]) is per-head constant -> cancels in softmax */
    const float* s_ret = (const float*)d_in[16];
    const float* b_ret = (const float*)d_in[17];
    const float* w_c3  = (const float*)d_in[18];
    const float* s_c3  = (const float*)d_in[19];
    const float* b_c3  = (const float*)d_in[20];
    const float* w_f1  = (const float*)d_in[21];
    const float* s_f1  = (const float*)d_in[22];
    const float* b_f1  = (const float*)d_in[23];
    const float* w_f2  = (const float*)d_in[24];
    const float* s_f2  = (const float*)d_in[25];
    const float* b_f2  = (const float*)d_in[26];

    float *ps, *pkv, *qs, *qkv, *ret, *qf, *ffn;
    cudaGetSymbolAddress((void**)&ps,  g_pixel_space);
    cudaGetSymbolAddress((void**)&pkv, g_pixel_kv);
    cudaGetSymbolAddress((void**)&qs,  g_query_space);
    cudaGetSymbolAddress((void**)&qkv, g_query_qkv);
    cudaGetSymbolAddress((void**)&ret, g_ret);
    cudaGetSymbolAddress((void**)&qf,  g_qf);
    cudaGetSymbolAddress((void**)&ffn, g_ffn);

    // pixel_space = gelu(bn(w_p1 @ gelu(pixel)))      M=256 K=2048 J=4096
    mma_gemm<1, 1><<<dim3(32, 2, 8), 256>>>(w_p1, pixel, s_p1, b_p1, nullptr, ps, 256, 2048, 4096);
    // query_space = gelu(bn(w_q1 @ query))            M=256 K=256  J=128
    mma_gemm<0, 1><<<dim3(1, 2, 8), 256>>>(w_q1, query, s_q1, b_q1, nullptr, qs, 256, 256, 128);
    // pixel_kv = bn(w_pkv @ pixel_space)              M=384 K=256  J=4096
    mma_gemm<0, 0><<<dim3(32, 3, 8), 256>>>(w_pkv, ps, s_pkv, b_pkv, nullptr, pkv, 384, 256, 4096);
    // query_qkv = bn(w_qkv @ query_space)             M=512 K=256  J=128
    mma_gemm<0, 0><<<dim3(1, 4, 8), 256>>>(w_qkv, qs, s_qkv, b_qkv, nullptr, qkv, 512, 256, 128);
    // fused attention -> g_ret
    attn_kernel<<<dim3(4, 8, 8), 256>>>(qkv, pkv, s_sim, s_ret, b_ret, ret);
    // qf = gelu(query + bn(w_c3 @ ret))               M=256 K=256  J=128
    mma_gemm<0, 2><<<dim3(1, 2, 8), 256>>>(w_c3, ret, s_c3, b_c3, query, qf, 256, 256, 128);
    // ffn = gelu(bn(w_f1 @ qf))                       M=2048 K=256 J=128
    mma_gemm<0, 1><<<dim3(1, 16, 8), 256>>>(w_f1, qf, s_f1, b_f1, nullptr, ffn, 2048, 256, 128);
    // out = gelu(qf + bn(w_f2 @ ffn))                 M=256 K=2048 J=128
    mma_gemm<0, 2><<<dim3(1, 2, 8), 256>>>(w_f2, ffn, s_f2, b_f2, qf, (float*)d_out, 256, 2048, 128);
}